// round 5
// baseline (speedup 1.0000x reference)
#include <cuda_runtime.h>
#include <cuda_bf16.h>
#include <cstdint>

// ---------------- problem constants ----------------
#define BB    128
#define QLQ   32
#define DLD   1024
#define HH    768
#define DIMD  128
#define KC    64          // K elements per gmem chunk
#define NCHUNK 12         // 768 / 64
#define NTILE 8           // 1024 / 128
#define NEGV  (-100000.0f)

// padded smem strides (bf16 elements) -> conflict-free ldmatrix, 16B-aligned rows
#define STRA  72          // A/W tiles: 64 cols + 8 pad (144 B/row)
#define STRD  136         // D/Q tiles: 128 cols + 8 pad (272 B/row)

// k_dscore smem layout (byte offsets)
#define OFF_A    0u                    // 128 x STRA bf16 = 18432
#define OFF_W    18432u                // 128 x STRA bf16 = 18432  (end 36864)
#define OFF_D    0u                    // 128 x STRD bf16 = 34816  (overlays A+W after GEMM1)
#define OFF_Q    36864u                // 32 x STRD bf16  = 8704   (end 45568)
#define OFF_N    45568u                // 128 x 2 float   = 1024   (end 46592)
#define OFF_R    46592u                // 8 x 32 float    = 1024   (end 47616)
#define SMEM_DS  47616
#define SMEM_QP  37888                 // A + W + norms

// ---------------- device scratch ----------------
__device__ __align__(16) __nv_bfloat16 g_Wb[DIMD * HH];          // 192 KB
__device__ __align__(16) __nv_bfloat16 g_Qb[BB * QLQ * DIMD];    // 1 MB
__device__ float g_part[BB * NTILE * QLQ];                       // 128 KB

// ---------------- helpers ----------------
static __device__ __forceinline__ uint32_t smem_u32(const void* p) {
    uint32_t a;
    asm("{ .reg .u64 t; cvta.to.shared.u64 t, %1; cvt.u32.u64 %0, t; }"
        : "=r"(a) : "l"(p));
    return a;
}

static __device__ __forceinline__ void ldsm_x4(uint32_t (&r)[4], uint32_t addr) {
    asm volatile("ldmatrix.sync.aligned.m8n8.x4.shared.b16 {%0,%1,%2,%3}, [%4];"
                 : "=r"(r[0]), "=r"(r[1]), "=r"(r[2]), "=r"(r[3]) : "r"(addr));
}
static __device__ __forceinline__ void mma_bf16(float (&d)[4], const uint32_t (&a)[4],
                                                const uint32_t* b) {
    asm volatile("mma.sync.aligned.m16n8k16.row.col.f32.bf16.bf16.f32 "
                 "{%0,%1,%2,%3}, {%4,%5,%6,%7}, {%8,%9}, {%0,%1,%2,%3};"
                 : "+f"(d[0]), "+f"(d[1]), "+f"(d[2]), "+f"(d[3])
                 : "r"(a[0]), "r"(a[1]), "r"(a[2]), "r"(a[3]), "r"(b[0]), "r"(b[1]));
}
static __device__ __forceinline__ uint32_t packbf2(float lo, float hi) {
    __nv_bfloat162 v = __floats2bfloat162_rn(lo, hi);   // lo -> .x (low half)
    return *reinterpret_cast<uint32_t*>(&v);
}

// ---------------- GEMM1 mainloop ----------------
// acc[2][8][4] (fp32) = bf16(Arows[128 x 768]) @ bf16(g_Wb[128 x 768])^T
// Warp tile: 32 rows (wm=w&3) x 64 cols (wn=w>>2). Single-buffered smem chunks
// with register prefetch of chunk k+1 overlapping the MMA of chunk k.
static __device__ __forceinline__ void gemm1(const float* __restrict__ a_rows,
                                             uint32_t sb,
                                             float (&acc)[2][8][4], int tid) {
    const int lane = tid & 31, w = tid >> 5;
    const int wm = w & 3, wn = w >> 2;
    const int lr = tid >> 1;                // 0..127 (load row for A and W)
    const int lc = (tid & 1) * 32;          // 0 or 32
    const float* aptr = a_rows + (size_t)lr * HH + lc;
    const __nv_bfloat16* wptr = g_Wb + (size_t)lr * HH + lc;

    float4 af[8]; uint4 wf[4];
#pragma unroll
    for (int i = 0; i < 8; ++i) af[i] = *(const float4*)(aptr + i * 4);
#pragma unroll
    for (int j = 0; j < 4; ++j) wf[j] = *(const uint4*)(wptr + j * 8);

    const uint32_t sA = sb + OFF_A, sW = sb + OFF_W;
    const uint32_t stA = sA + (uint32_t)(lr * STRA + lc) * 2;
    const uint32_t stW = sW + (uint32_t)(lr * STRA + lc) * 2;

    // per-warp ldmatrix source addresses (lane-dependent parts precomputed)
    const uint32_t ldA = sA + (uint32_t)((wm * 32 + (lane & 15)) * STRA
                                         + (lane >> 4) * 8) * 2;
    // B x4: lanes 0-7 -> rows nt*8+l (k lo), 8-15 -> same rows (k hi),
    //       16-23 -> rows (nt+1)*8+l (k lo), 24-31 -> (k hi)
    const uint32_t ldB = sW + (uint32_t)((wn * 64 + ((lane >> 4) & 1) * 8 + (lane & 7)) * STRA
                                         + ((lane >> 3) & 1) * 8) * 2;

    for (int kc = 0; kc < NCHUNK; ++kc) {
        __syncthreads();    // previous chunk's ldmatrix reads complete
#pragma unroll
        for (int i = 0; i < 8; ++i) {
            uint32_t p0 = packbf2(af[i].x, af[i].y);
            uint32_t p1 = packbf2(af[i].z, af[i].w);
            asm volatile("st.shared.v2.b32 [%0], {%1, %2};"
                         :: "r"(stA + i * 8u), "r"(p0), "r"(p1) : "memory");
        }
#pragma unroll
        for (int j = 0; j < 4; ++j)
            asm volatile("st.shared.v4.b32 [%0], {%1, %2, %3, %4};"
                         :: "r"(stW + j * 16u),
                            "r"(wf[j].x), "r"(wf[j].y), "r"(wf[j].z), "r"(wf[j].w)
                         : "memory");
        __syncthreads();
        if (kc + 1 < NCHUNK) {
            const float* ap = aptr + (kc + 1) * KC;
            const __nv_bfloat16* wp = wptr + (kc + 1) * KC;
#pragma unroll
            for (int i = 0; i < 8; ++i) af[i] = *(const float4*)(ap + i * 4);
#pragma unroll
            for (int j = 0; j < 4; ++j) wf[j] = *(const uint4*)(wp + j * 8);
        }
#pragma unroll
        for (int ks = 0; ks < 4; ++ks) {
            uint32_t afr[2][4];
#pragma unroll
            for (int mt = 0; mt < 2; ++mt)
                ldsm_x4(afr[mt], ldA + (uint32_t)(mt * 16 * STRA + ks * 16) * 2);
#pragma unroll
            for (int np = 0; np < 4; ++np) {     // nt pairs: (0,1),(2,3),(4,5),(6,7)
                uint32_t bfr[4];
                ldsm_x4(bfr, ldB + (uint32_t)(np * 16 * STRA + ks * 16) * 2);
                mma_bf16(acc[0][np * 2],     afr[0], bfr);
                mma_bf16(acc[1][np * 2],     afr[1], bfr);
                mma_bf16(acc[0][np * 2 + 1], afr[0], bfr + 2);
                mma_bf16(acc[1][np * 2 + 1], afr[1], bfr + 2);
            }
        }
    }
}

// ---------------- kernel 0: W -> bf16 ----------------
__global__ void k_prep(const float* __restrict__ W) {
    int i = blockIdx.x * blockDim.x + threadIdx.x;
    if (i < DIMD * HH) g_Wb[i] = __float2bfloat16(W[i]);
}

// ---------------- kernel 1: Q projection + L2 normalize -> g_Qb ----------------
__global__ void __launch_bounds__(256) k_qproj(const float* __restrict__ Q_emb) {
    extern __shared__ char dyn[];
    uint32_t sb = smem_u32(dyn);
    const int tid = threadIdx.x, lane = tid & 31, w = tid >> 5;
    const int wm = w & 3, wn = w >> 2;

    float acc[2][8][4] = {};
    gemm1(Q_emb + (size_t)blockIdx.x * 128 * HH, sb, acc, tid);

    float* nrm = (float*)(dyn + SMEM_QP - 1024);   // 128 x 2 floats
    // partial row sums of squares -> quad-reduce -> smem
#pragma unroll
    for (int mt = 0; mt < 2; ++mt)
#pragma unroll
        for (int rs = 0; rs < 2; ++rs) {
            int gr = wm * 32 + mt * 16 + rs * 8 + (lane >> 2);
            float s = 0.f;
#pragma unroll
            for (int nt = 0; nt < 8; ++nt) {
                float x = acc[mt][nt][rs * 2], y = acc[mt][nt][rs * 2 + 1];
                s = fmaf(x, x, fmaf(y, y, s));
            }
            s += __shfl_xor_sync(0xFFFFFFFFu, s, 1);
            s += __shfl_xor_sync(0xFFFFFFFFu, s, 2);
            if ((lane & 3) == 0) nrm[gr * 2 + wn] = s;
        }
    __syncthreads();
    if (tid < 128) {
        float s = nrm[tid * 2] + nrm[tid * 2 + 1];
        nrm[tid * 2] = rsqrtf(fmaxf(s, 1e-24f));
    }
    __syncthreads();
#pragma unroll
    for (int mt = 0; mt < 2; ++mt)
#pragma unroll
        for (int rs = 0; rs < 2; ++rs) {
            int gr = wm * 32 + mt * 16 + rs * 8 + (lane >> 2);
            float iv = nrm[gr * 2];
            size_t row = (size_t)blockIdx.x * 128 + gr;
#pragma unroll
            for (int nt = 0; nt < 8; ++nt) {
                int col = wn * 64 + nt * 8 + (lane & 3) * 2;
                uint32_t p = packbf2(acc[mt][nt][rs * 2] * iv, acc[mt][nt][rs * 2 + 1] * iv);
                *(uint32_t*)(g_Qb + row * DIMD + col) = p;
            }
        }
}

// ---------------- kernel 2: D projection + scoring ----------------
__global__ void __launch_bounds__(256)
k_dscore(const float* __restrict__ D_emb,
         const int* __restrict__ doc_ids,
         const int* __restrict__ doc_attn) {
    extern __shared__ char dyn[];
    uint32_t sb = smem_u32(dyn);
    const int tid = threadIdx.x, lane = tid & 31, w = tid >> 5;
    const int wm = w & 3, wn = w >> 2;
    const int tile = blockIdx.x, b = blockIdx.y;

    // stage Q tile (32 x 128 bf16) into OFF_Q (disjoint from GEMM1 tiles)
#pragma unroll
    for (int g = tid; g < 512; g += 256) {
        int qr = g >> 4, qc = (g & 15) * 8;
        uint4 v = *(const uint4*)(g_Qb + ((size_t)b * QLQ + qr) * DIMD + qc);
        *(uint4*)(dyn + OFF_Q + (qr * STRD + qc) * 2) = v;
    }

    float acc[2][8][4] = {};
    gemm1(D_emb + ((size_t)b * DLD + (size_t)tile * 128) * HH, sb, acc, tid);
    __syncthreads();   // all warps done reading A/W smem before D overlay

    float* nrm = (float*)(dyn + OFF_N);
    const uint32_t sD = sb + OFF_D;
    // epilogue 1: row sq-sums + bf16 convert into smem D tile
#pragma unroll
    for (int mt = 0; mt < 2; ++mt)
#pragma unroll
        for (int rs = 0; rs < 2; ++rs) {
            int gr = wm * 32 + mt * 16 + rs * 8 + (lane >> 2);
            float s = 0.f;
#pragma unroll
            for (int nt = 0; nt < 8; ++nt) {
                float x = acc[mt][nt][rs * 2], y = acc[mt][nt][rs * 2 + 1];
                s = fmaf(x, x, fmaf(y, y, s));
                int col = wn * 64 + nt * 8 + (lane & 3) * 2;
                uint32_t p = packbf2(x, y);
                asm volatile("st.shared.b32 [%0], %1;"
                             :: "r"(sD + (uint32_t)(gr * STRD + col) * 2), "r"(p) : "memory");
            }
            s += __shfl_xor_sync(0xFFFFFFFFu, s, 1);
            s += __shfl_xor_sync(0xFFFFFFFFu, s, 2);
            if ((lane & 3) == 0) nrm[gr * 2 + wn] = s;
        }
    __syncthreads();
    if (tid < 128) {
        float s = nrm[tid * 2] + nrm[tid * 2 + 1];
        nrm[tid * 2] = rsqrtf(fmaxf(s, 1e-24f));
    }
    __syncthreads();

    // GEMM2: [128 tokens x 32 queries] = D_tile(bf16) @ Q_tile^T, K = 128
    const uint32_t sQ = sb + OFF_Q;
    const uint32_t ldA2 = sD + (uint32_t)((w * 16 + (lane & 15)) * STRD
                                          + (lane >> 4) * 8) * 2;
    const uint32_t ldB2 = sQ + (uint32_t)((((lane >> 4) & 1) * 8 + (lane & 7)) * STRD
                                          + ((lane >> 3) & 1) * 8) * 2;
    float acc2[4][4] = {};
#pragma unroll
    for (int ks = 0; ks < 8; ++ks) {
        uint32_t afr[4];
        ldsm_x4(afr, ldA2 + (uint32_t)(ks * 16) * 2);
#pragma unroll
        for (int np = 0; np < 2; ++np) {     // nt pairs (0,1),(2,3)
            uint32_t bfr[4];
            ldsm_x4(bfr, ldB2 + (uint32_t)(np * 16 * STRD + ks * 16) * 2);
            mma_bf16(acc2[np * 2],     afr, bfr);
            mma_bf16(acc2[np * 2 + 1], afr, bfr + 2);
        }
    }

    // epilogue 2: masked score + max over this warp's 16 token rows
    const int tb = b * DLD + tile * 128;
    const int r0 = w * 16 + (lane >> 2), r1 = r0 + 8;
    const float iv0 = nrm[r0 * 2], iv1 = nrm[r1 * 2];
    const int id0 = doc_ids[tb + r0], id1 = doc_ids[tb + r1];
    const int at0 = doc_attn[tb + r0], at1 = doc_attn[tb + r1];
    float colmax[8];
#pragma unroll
    for (int nt = 0; nt < 4; ++nt)
#pragma unroll
        for (int c = 0; c < 2; ++c) {
            float v0 = at0 ? (id0 ? fmaf(2.f * iv0, acc2[nt][c], -2.f) : -1.f) : NEGV;
            float v1 = at1 ? (id1 ? fmaf(2.f * iv1, acc2[nt][2 + c], -2.f) : -1.f) : NEGV;
            colmax[nt * 2 + c] = fmaxf(v0, v1);
        }
#pragma unroll
    for (int s = 4; s < 32; s <<= 1)
#pragma unroll
        for (int j = 0; j < 8; ++j)
            colmax[j] = fmaxf(colmax[j], __shfl_xor_sync(0xFFFFFFFFu, colmax[j], s));

    float* red = (float*)(dyn + OFF_R);
    if (lane < 4)
#pragma unroll
        for (int nt = 0; nt < 4; ++nt)
#pragma unroll
            for (int c = 0; c < 2; ++c)
                red[w * 32 + nt * 8 + lane * 2 + c] = colmax[nt * 2 + c];
    __syncthreads();
    if (tid < 32) {
        float m = -3.0e38f;
#pragma unroll
        for (int ww = 0; ww < 8; ++ww) m = fmaxf(m, red[ww * 32 + tid]);
        g_part[((size_t)b * NTILE + tile) * QLQ + tid] = m;
    }
}

// ---------------- kernel 3: combine tiles -> out[B] ----------------
__global__ void k_final(float* __restrict__ out) {
    int b = blockIdx.x, q = threadIdx.x;
    float m = -3.0e38f;
#pragma unroll
    for (int t = 0; t < NTILE; ++t)
        m = fmaxf(m, g_part[((size_t)b * NTILE + t) * QLQ + q]);
#pragma unroll
    for (int s = 16; s > 0; s >>= 1)
        m += __shfl_xor_sync(0xFFFFFFFFu, m, s);
    if (q == 0) out[b] = m;
}

// ---------------- launch ----------------
extern "C" void kernel_launch(void* const* d_in, const int* in_sizes, int n_in,
                              void* d_out, int out_size) {
    const float* Q_emb = (const float*)d_in[0];
    const float* D_emb = (const float*)d_in[1];
    const int*   ids   = (const int*)d_in[2];
    const int*   attn  = (const int*)d_in[3];
    const float* W     = (const float*)d_in[4];
    float* out = (float*)d_out;

    k_prep<<<(DIMD * HH + 255) / 256, 256>>>(W);
    k_qproj<<<32, 256, SMEM_QP>>>(Q_emb);
    k_dscore<<<dim3(NTILE, BB), 256, SMEM_DS>>>(D_emb, ids, attn);
    k_final<<<BB, 32>>>(out);
}

// round 7
// speedup vs baseline: 1.1564x; 1.1564x over previous
#include <cuda_runtime.h>
#include <cuda_bf16.h>
#include <cstdint>

// ---------------- problem constants ----------------
#define BB    128
#define QLQ   32
#define DLD   1024
#define HH    768
#define DIMD  128
#define KC    64          // K elements per gmem chunk
#define NCHUNK 12         // 768 / 64
#define NTILE 8           // 1024 / 128
#define NEGV  (-100000.0f)
#define NTHREADS 512

// padded smem strides (bf16 elements) -> conflict-free ldmatrix, 16B-aligned rows
#define STRA  72          // A/W tiles: 64 cols + 8 pad (144 B/row)
#define STRD  136         // D/Q tiles: 128 cols + 8 pad (272 B/row)

// k_dscore smem layout (byte offsets)
#define OFF_A    0u                    // 128 x STRA bf16 = 18432
#define OFF_W    18432u                // 128 x STRA bf16 = 18432  (end 36864)
#define OFF_D    0u                    // 128 x STRD bf16 = 34816  (overlays A+W after GEMM1)
#define OFF_Q    36864u                // 32 x STRD bf16  = 8704   (end 45568)
#define OFF_N    45568u                // 128 x 4 float   = 2048   (end 47616)
#define OFF_R    47616u                // 8 x 32 float    = 1024   (end 48640)
#define SMEM_DS  48640                 // < 49152 default limit
#define SMEM_QP  38912                 // A + W + norms(2048)

// ---------------- device scratch ----------------
__device__ __align__(16) __nv_bfloat16 g_Wb[DIMD * HH];          // 192 KB
__device__ __align__(16) __nv_bfloat16 g_Qb[BB * QLQ * DIMD];    // 1 MB
__device__ float g_part[BB * NTILE * QLQ];                       // 128 KB

// ---------------- helpers ----------------
static __device__ __forceinline__ uint32_t smem_u32(const void* p) {
    uint32_t a;
    asm("{ .reg .u64 t; cvta.to.shared.u64 t, %1; cvt.u32.u64 %0, t; }"
        : "=r"(a) : "l"(p));
    return a;
}

static __device__ __forceinline__ void ldsm_x4(uint32_t (&r)[4], uint32_t addr) {
    asm volatile("ldmatrix.sync.aligned.m8n8.x4.shared.b16 {%0,%1,%2,%3}, [%4];"
                 : "=r"(r[0]), "=r"(r[1]), "=r"(r[2]), "=r"(r[3]) : "r"(addr));
}
static __device__ __forceinline__ void mma_bf16(float (&d)[4], const uint32_t (&a)[4],
                                                const uint32_t* b) {
    asm volatile("mma.sync.aligned.m16n8k16.row.col.f32.bf16.bf16.f32 "
                 "{%0,%1,%2,%3}, {%4,%5,%6,%7}, {%8,%9}, {%0,%1,%2,%3};"
                 : "+f"(d[0]), "+f"(d[1]), "+f"(d[2]), "+f"(d[3])
                 : "r"(a[0]), "r"(a[1]), "r"(a[2]), "r"(a[3]), "r"(b[0]), "r"(b[1]));
}
static __device__ __forceinline__ uint32_t packbf2(float lo, float hi) {
    __nv_bfloat162 v = __floats2bfloat162_rn(lo, hi);   // lo -> .x (low half)
    return *reinterpret_cast<uint32_t*>(&v);
}

// ---------------- GEMM1 mainloop (512 threads, 16 warps) ----------------
// acc[2][4][4] (fp32) = bf16(Arows[128 x 768]) @ bf16(g_Wb[128 x 768])^T
// Warp tile: 32 rows (wm=w&3) x 32 cols (wn=w>>2). Single-buffered smem chunks
// with register prefetch of chunk k+1 overlapping the MMA of chunk k.
static __device__ __forceinline__ void gemm1(const float* __restrict__ a_rows,
                                             uint32_t sb,
                                             float (&acc)[2][4][4], int tid) {
    const int lane = tid & 31, w = tid >> 5;
    const int wm = w & 3, wn = w >> 2;          // wn in 0..3
    const int lr = tid >> 2;                    // 0..127 (load row)
    const int lc = (tid & 3) * 16;              // 0,16,32,48
    const float* aptr = a_rows + (size_t)lr * HH + lc;
    const __nv_bfloat16* wptr = g_Wb + (size_t)lr * HH + lc;

    float4 af[4]; uint4 wf[2];
#pragma unroll
    for (int i = 0; i < 4; ++i) af[i] = *(const float4*)(aptr + i * 4);
#pragma unroll
    for (int j = 0; j < 2; ++j) wf[j] = *(const uint4*)(wptr + j * 8);

    const uint32_t sA = sb + OFF_A, sW = sb + OFF_W;
    const uint32_t stA = sA + (uint32_t)(lr * STRA + lc) * 2;
    const uint32_t stW = sW + (uint32_t)(lr * STRA + lc) * 2;

    // per-warp ldmatrix source addresses
    const uint32_t ldA = sA + (uint32_t)((wm * 32 + (lane & 15)) * STRA
                                         + (lane >> 4) * 8) * 2;
    // fused B x4: lanes 0-7 rows nt*8+l (k lo), 8-15 (k hi), 16-31 -> nt+1
    const uint32_t ldB = sW + (uint32_t)((wn * 32 + ((lane >> 4) & 1) * 8 + (lane & 7)) * STRA
                                         + ((lane >> 3) & 1) * 8) * 2;

    for (int kc = 0; kc < NCHUNK; ++kc) {
        __syncthreads();    // previous chunk's ldmatrix reads complete
#pragma unroll
        for (int i = 0; i < 4; ++i) {
            uint32_t p0 = packbf2(af[i].x, af[i].y);
            uint32_t p1 = packbf2(af[i].z, af[i].w);
            asm volatile("st.shared.v2.b32 [%0], {%1, %2};"
                         :: "r"(stA + i * 8u), "r"(p0), "r"(p1) : "memory");
        }
#pragma unroll
        for (int j = 0; j < 2; ++j)
            asm volatile("st.shared.v4.b32 [%0], {%1, %2, %3, %4};"
                         :: "r"(stW + j * 16u),
                            "r"(wf[j].x), "r"(wf[j].y), "r"(wf[j].z), "r"(wf[j].w)
                         : "memory");
        __syncthreads();
        if (kc + 1 < NCHUNK) {
            const float* ap = aptr + (kc + 1) * KC;
            const __nv_bfloat16* wp = wptr + (kc + 1) * KC;
#pragma unroll
            for (int i = 0; i < 4; ++i) af[i] = *(const float4*)(ap + i * 4);
#pragma unroll
            for (int j = 0; j < 2; ++j) wf[j] = *(const uint4*)(wp + j * 8);
        }
#pragma unroll
        for (int ks = 0; ks < 4; ++ks) {
            uint32_t afr[2][4];
#pragma unroll
            for (int mt = 0; mt < 2; ++mt)
                ldsm_x4(afr[mt], ldA + (uint32_t)(mt * 16 * STRA + ks * 16) * 2);
#pragma unroll
            for (int np = 0; np < 2; ++np) {     // nt pairs (0,1),(2,3)
                uint32_t bfr[4];
                ldsm_x4(bfr, ldB + (uint32_t)(np * 16 * STRA + ks * 16) * 2);
                mma_bf16(acc[0][np * 2],     afr[0], bfr);
                mma_bf16(acc[1][np * 2],     afr[1], bfr);
                mma_bf16(acc[0][np * 2 + 1], afr[0], bfr + 2);
                mma_bf16(acc[1][np * 2 + 1], afr[1], bfr + 2);
            }
        }
    }
}

// ---------------- kernel 0: W -> bf16 ----------------
__global__ void k_prep(const float* __restrict__ W) {
    int i = blockIdx.x * blockDim.x + threadIdx.x;
    if (i < DIMD * HH) g_Wb[i] = __float2bfloat16(W[i]);
}

// ---------------- kernel 1: Q projection + L2 normalize -> g_Qb ----------------
__global__ void __launch_bounds__(NTHREADS) k_qproj(const float* __restrict__ Q_emb) {
    extern __shared__ char dyn[];
    uint32_t sb = smem_u32(dyn);
    const int tid = threadIdx.x, lane = tid & 31, w = tid >> 5;
    const int wm = w & 3, wn = w >> 2;

    float acc[2][4][4] = {};
    gemm1(Q_emb + (size_t)blockIdx.x * 128 * HH, sb, acc, tid);

    float* nrm = (float*)(dyn + SMEM_QP - 2048);   // 128 x 4 floats (disjoint from A/W)
#pragma unroll
    for (int mt = 0; mt < 2; ++mt)
#pragma unroll
        for (int rs = 0; rs < 2; ++rs) {
            int gr = wm * 32 + mt * 16 + rs * 8 + (lane >> 2);
            float s = 0.f;
#pragma unroll
            for (int nt = 0; nt < 4; ++nt) {
                float x = acc[mt][nt][rs * 2], y = acc[mt][nt][rs * 2 + 1];
                s = fmaf(x, x, fmaf(y, y, s));
            }
            s += __shfl_xor_sync(0xFFFFFFFFu, s, 1);
            s += __shfl_xor_sync(0xFFFFFFFFu, s, 2);
            if ((lane & 3) == 0) nrm[gr * 4 + wn] = s;
        }
    __syncthreads();
    if (tid < 128) {
        float s = nrm[tid * 4] + nrm[tid * 4 + 1] + nrm[tid * 4 + 2] + nrm[tid * 4 + 3];
        nrm[tid * 4] = rsqrtf(fmaxf(s, 1e-24f));
    }
    __syncthreads();
#pragma unroll
    for (int mt = 0; mt < 2; ++mt)
#pragma unroll
        for (int rs = 0; rs < 2; ++rs) {
            int gr = wm * 32 + mt * 16 + rs * 8 + (lane >> 2);
            float iv = nrm[gr * 4];
            size_t row = (size_t)blockIdx.x * 128 + gr;
#pragma unroll
            for (int nt = 0; nt < 4; ++nt) {
                int col = wn * 32 + nt * 8 + (lane & 3) * 2;
                uint32_t p = packbf2(acc[mt][nt][rs * 2] * iv, acc[mt][nt][rs * 2 + 1] * iv);
                *(uint32_t*)(g_Qb + row * DIMD + col) = p;
            }
        }
}

// ---------------- kernel 2: D projection + scoring ----------------
__global__ void __launch_bounds__(NTHREADS)
k_dscore(const float* __restrict__ D_emb,
         const int* __restrict__ doc_ids,
         const int* __restrict__ doc_attn) {
    extern __shared__ char dyn[];
    uint32_t sb = smem_u32(dyn);
    const int tid = threadIdx.x, lane = tid & 31, w = tid >> 5;
    const int wm = w & 3, wn = w >> 2;
    const int tile = blockIdx.x, b = blockIdx.y;

    // stage Q tile (32 x 128 bf16) into OFF_Q (disjoint from GEMM1 tiles)
    for (int g = tid; g < 512; g += NTHREADS) {
        int qr = g >> 4, qc = (g & 15) * 8;
        uint4 v = *(const uint4*)(g_Qb + ((size_t)b * QLQ + qr) * DIMD + qc);
        *(uint4*)(dyn + OFF_Q + (qr * STRD + qc) * 2) = v;
    }

    float acc[2][4][4] = {};
    gemm1(D_emb + ((size_t)b * DLD + (size_t)tile * 128) * HH, sb, acc, tid);
    __syncthreads();   // all warps done reading A/W smem before D overlay

    float* nrm = (float*)(dyn + OFF_N);
    const uint32_t sD = sb + OFF_D;
    // epilogue 1: row sq-sums + bf16 convert into smem D tile
#pragma unroll
    for (int mt = 0; mt < 2; ++mt)
#pragma unroll
        for (int rs = 0; rs < 2; ++rs) {
            int gr = wm * 32 + mt * 16 + rs * 8 + (lane >> 2);
            float s = 0.f;
#pragma unroll
            for (int nt = 0; nt < 4; ++nt) {
                float x = acc[mt][nt][rs * 2], y = acc[mt][nt][rs * 2 + 1];
                s = fmaf(x, x, fmaf(y, y, s));
                int col = wn * 32 + nt * 8 + (lane & 3) * 2;
                uint32_t p = packbf2(x, y);
                asm volatile("st.shared.b32 [%0], %1;"
                             :: "r"(sD + (uint32_t)(gr * STRD + col) * 2), "r"(p) : "memory");
            }
            s += __shfl_xor_sync(0xFFFFFFFFu, s, 1);
            s += __shfl_xor_sync(0xFFFFFFFFu, s, 2);
            if ((lane & 3) == 0) nrm[gr * 4 + wn] = s;
        }
    __syncthreads();
    if (tid < 128) {
        float s = nrm[tid * 4] + nrm[tid * 4 + 1] + nrm[tid * 4 + 2] + nrm[tid * 4 + 3];
        nrm[tid * 4] = rsqrtf(fmaxf(s, 1e-24f));
    }
    __syncthreads();

    // GEMM2 (warps 0-7): [128 tokens x 32 queries] = D_tile(bf16) @ Q_tile^T, K=128
    if (w < 8) {
        const uint32_t sQ = sb + OFF_Q;
        const uint32_t ldA2 = sD + (uint32_t)((w * 16 + (lane & 15)) * STRD
                                              + (lane >> 4) * 8) * 2;
        const uint32_t ldB2 = sQ + (uint32_t)((((lane >> 4) & 1) * 8 + (lane & 7)) * STRD
                                              + ((lane >> 3) & 1) * 8) * 2;
        float acc2[4][4] = {};
#pragma unroll
        for (int ks = 0; ks < 8; ++ks) {
            uint32_t afr[4];
            ldsm_x4(afr, ldA2 + (uint32_t)(ks * 16) * 2);
#pragma unroll
            for (int np = 0; np < 2; ++np) {     // nt pairs (0,1),(2,3)
                uint32_t bfr[4];
                ldsm_x4(bfr, ldB2 + (uint32_t)(np * 16 * STRD + ks * 16) * 2);
                mma_bf16(acc2[np * 2],     afr, bfr);
                mma_bf16(acc2[np * 2 + 1], afr, bfr + 2);
            }
        }

        // epilogue 2: masked score + max over this warp's 16 token rows
        const int tb = b * DLD + tile * 128;
        const int r0 = w * 16 + (lane >> 2), r1 = r0 + 8;
        const float iv0 = nrm[r0 * 4], iv1 = nrm[r1 * 4];
        const int id0 = doc_ids[tb + r0], id1 = doc_ids[tb + r1];
        const int at0 = doc_attn[tb + r0], at1 = doc_attn[tb + r1];
        float colmax[8];
#pragma unroll
        for (int nt = 0; nt < 4; ++nt)
#pragma unroll
            for (int c = 0; c < 2; ++c) {
                float v0 = at0 ? (id0 ? fmaf(2.f * iv0, acc2[nt][c], -2.f) : -1.f) : NEGV;
                float v1 = at1 ? (id1 ? fmaf(2.f * iv1, acc2[nt][2 + c], -2.f) : -1.f) : NEGV;
                colmax[nt * 2 + c] = fmaxf(v0, v1);
            }
#pragma unroll
        for (int s = 4; s < 32; s <<= 1)
#pragma unroll
            for (int j = 0; j < 8; ++j)
                colmax[j] = fmaxf(colmax[j], __shfl_xor_sync(0xFFFFFFFFu, colmax[j], s));

        float* red = (float*)(dyn + OFF_R);
        if (lane < 4)
#pragma unroll
            for (int nt = 0; nt < 4; ++nt)
#pragma unroll
                for (int c = 0; c < 2; ++c)
                    red[w * 32 + nt * 8 + lane * 2 + c] = colmax[nt * 2 + c];
    }
    __syncthreads();
    if (tid < 32) {
        float* red = (float*)(dyn + OFF_R);
        float m = -3.0e38f;
#pragma unroll
        for (int ww = 0; ww < 8; ++ww) m = fmaxf(m, red[ww * 32 + tid]);
        g_part[((size_t)b * NTILE + tile) * QLQ + tid] = m;
    }
}

// ---------------- kernel 3: combine tiles -> out[B] ----------------
__global__ void k_final(float* __restrict__ out) {
    int b = blockIdx.x, q = threadIdx.x;
    float m = -3.0e38f;
#pragma unroll
    for (int t = 0; t < NTILE; ++t)
        m = fmaxf(m, g_part[((size_t)b * NTILE + t) * QLQ + q]);
#pragma unroll
    for (int s = 16; s > 0; s >>= 1)
        m += __shfl_xor_sync(0xFFFFFFFFu, m, s);
    if (q == 0) out[b] = m;
}

// ---------------- launch ----------------
extern "C" void kernel_launch(void* const* d_in, const int* in_sizes, int n_in,
                              void* d_out, int out_size) {
    const float* Q_emb = (const float*)d_in[0];
    const float* D_emb = (const float*)d_in[1];
    const int*   ids   = (const int*)d_in[2];
    const int*   attn  = (const int*)d_in[3];
    const float* W     = (const float*)d_in[4];
    float* out = (float*)d_out;

    k_prep<<<(DIMD * HH + 255) / 256, 256>>>(W);
    k_qproj<<<32, NTHREADS, SMEM_QP>>>(Q_emb);
    k_dscore<<<dim3(NTILE, BB), NTHREADS, SMEM_DS>>>(D_emb, ids, attn);
    k_final<<<BB, 32>>>(out);
}

// round 9
// speedup vs baseline: 1.3421x; 1.1606x over previous
#include <cuda_runtime.h>
#include <cuda_bf16.h>
#include <cstdint>

// ---------------- problem constants ----------------
#define BB    128
#define QLQ   32
#define DLD   1024
#define HH    768
#define DIMD  128
#define KC    64          // K elements per chunk
#define NCHUNK 12         // 768 / 64
#define NTILE 8           // 1024 / 128
#define NEGV  (-100000.0f)
#define NTHREADS 512

// padded smem strides (bf16 elements) -> conflict-free ldmatrix, 16B-aligned rows
#define STRA  72          // A/W tiles: 64 cols + 8 pad (144 B/row)
#define STRD  136         // D/Q tiles: 128 cols + 8 pad (272 B/row)

// smem layout (byte offsets) — two stages of (A,W) for the pipelined mainloop
#define OFF_S0A  0u                    // stage0 A: 18432
#define OFF_S0W  18432u                // stage0 W: 18432   (stage0 end 36864)
#define OFF_S1A  36864u                // stage1 A: 18432
#define OFF_S1W  55296u                // stage1 W: 18432   (stage1 end 73728)
#define OFF_D    0u                    // D tile 128 x STRD bf16 = 34816 (overlays stage0)
#define OFF_Q    73728u                // Q tile 32 x STRD bf16 = 8704  (end 82432)
#define OFF_N    82432u                // 128 x 4 float = 2048          (end 84480)
#define OFF_R    84480u                // 8 x 32 float  = 1024          (end 85504)
#define SMEM_DS  85504
#define OFF_NQ   73728u                // k_qproj norms
#define SMEM_QP  75776

// ---------------- device scratch ----------------
__device__ __align__(16) __nv_bfloat16 g_Wb[DIMD * HH];          // 192 KB
__device__ __align__(16) __nv_bfloat16 g_Qb[BB * QLQ * DIMD];    // 1 MB
__device__ float g_part[BB * NTILE * QLQ];                       // 128 KB

// ---------------- helpers ----------------
static __device__ __forceinline__ uint32_t smem_u32(const void* p) {
    uint32_t a;
    asm("{ .reg .u64 t; cvta.to.shared.u64 t, %1; cvt.u32.u64 %0, t; }"
        : "=r"(a) : "l"(p));
    return a;
}
static __device__ __forceinline__ void ldsm_x4(uint32_t (&r)[4], uint32_t addr) {
    asm volatile("ldmatrix.sync.aligned.m8n8.x4.shared.b16 {%0,%1,%2,%3}, [%4];"
                 : "=r"(r[0]), "=r"(r[1]), "=r"(r[2]), "=r"(r[3]) : "r"(addr));
}
static __device__ __forceinline__ void mma_bf16(float (&d)[4], const uint32_t (&a)[4],
                                                const uint32_t* b) {
    asm volatile("mma.sync.aligned.m16n8k16.row.col.f32.bf16.bf16.f32 "
                 "{%0,%1,%2,%3}, {%4,%5,%6,%7}, {%8,%9}, {%0,%1,%2,%3};"
                 : "+f"(d[0]), "+f"(d[1]), "+f"(d[2]), "+f"(d[3])
                 : "r"(a[0]), "r"(a[1]), "r"(a[2]), "r"(a[3]), "r"(b[0]), "r"(b[1]));
}
static __device__ __forceinline__ uint32_t packbf2(float lo, float hi) {
    __nv_bfloat162 v = __floats2bfloat162_rn(lo, hi);
    return *reinterpret_cast<uint32_t*>(&v);
}
static __device__ __forceinline__ void cp16(uint32_t dst, const void* src) {
    asm volatile("cp.async.cg.shared.global [%0], [%1], 16;"
                 :: "r"(dst), "l"(src) : "memory");
}
#define CP_COMMIT() asm volatile("cp.async.commit_group;" ::: "memory")
#define CP_WAIT0()  asm volatile("cp.async.wait_group 0;" ::: "memory")

// ---------------- GEMM1 mainloop (2-stage pipeline, 1 sync/chunk) ----------------
// acc[2][4][4] = bf16(Arows[128x768]) @ bf16(g_Wb[128x768])^T
// Warp tile 32(wm) x 32(wn). A: LDG fp32 -> cvt -> STS (stage nxt). W: cp.async.
static __device__ __forceinline__ void gemm1(const float* __restrict__ a_rows,
                                             uint32_t sb,
                                             float (&acc)[2][4][4], int tid) {
    const int lane = tid & 31, w = tid >> 5;
    const int wm = w & 3, wn = w >> 2;
    const int lr = tid >> 2;                    // 0..127 load row
    const int lc = (tid & 3) * 16;              // 0,16,32,48
    const float* aptr = a_rows + (size_t)lr * HH + lc;
    const __nv_bfloat16* wsrc = g_Wb + (size_t)lr * HH + lc;

    const uint32_t sA[2] = {sb + OFF_S0A, sb + OFF_S1A};
    const uint32_t sW[2] = {sb + OFF_S0W, sb + OFF_S1W};
    const uint32_t stO = (uint32_t)(lr * STRA + lc) * 2;   // byte offset within tile
    const uint32_t ldAo = (uint32_t)((wm * 32 + (lane & 15)) * STRA + (lane >> 4) * 8) * 2;
    const uint32_t ldBo = (uint32_t)((wn * 32 + ((lane >> 4) & 1) * 8 + (lane & 7)) * STRA
                                     + ((lane >> 3) & 1) * 8) * 2;

    float4 af[4];
    // ---- prologue: chunk 0 -> stage 0, prefetch chunk 1 into regs
#pragma unroll
    for (int i = 0; i < 4; ++i) af[i] = *(const float4*)(aptr + i * 4);
    cp16(sW[0] + stO, wsrc);
    cp16(sW[0] + stO + 16u, wsrc + 8);
    CP_COMMIT();
#pragma unroll
    for (int i = 0; i < 4; ++i) {
        uint32_t p0 = packbf2(af[i].x, af[i].y);
        uint32_t p1 = packbf2(af[i].z, af[i].w);
        asm volatile("st.shared.v2.b32 [%0], {%1, %2};"
                     :: "r"(sA[0] + stO + i * 8u), "r"(p0), "r"(p1) : "memory");
    }
#pragma unroll
    for (int i = 0; i < 4; ++i) af[i] = *(const float4*)(aptr + KC + i * 4);
    CP_WAIT0();
    __syncthreads();

    for (int kc = 0; kc < NCHUNK; ++kc) {
        const int cur = kc & 1, nxt = cur ^ 1;
        if (kc + 1 < NCHUNK) {
            // STS A(kc+1) into stage nxt (regs loaded last iteration)
#pragma unroll
            for (int i = 0; i < 4; ++i) {
                uint32_t p0 = packbf2(af[i].x, af[i].y);
                uint32_t p1 = packbf2(af[i].z, af[i].w);
                asm volatile("st.shared.v2.b32 [%0], {%1, %2};"
                             :: "r"(sA[nxt] + stO + i * 8u), "r"(p0), "r"(p1) : "memory");
            }
            const __nv_bfloat16* wp = wsrc + (kc + 1) * KC;
            cp16(sW[nxt] + stO, wp);
            cp16(sW[nxt] + stO + 16u, wp + 8);
            CP_COMMIT();
            if (kc + 2 < NCHUNK) {
                const float* ap = aptr + (kc + 2) * KC;
#pragma unroll
                for (int i = 0; i < 4; ++i) af[i] = *(const float4*)(ap + i * 4);
            }
        }
        // ---- MMA on stage cur
#pragma unroll
        for (int ks = 0; ks < 4; ++ks) {
            uint32_t afr[2][4];
#pragma unroll
            for (int mt = 0; mt < 2; ++mt)
                ldsm_x4(afr[mt], sA[cur] + ldAo + (uint32_t)(mt * 16 * STRA + ks * 16) * 2);
#pragma unroll
            for (int np = 0; np < 2; ++np) {
                uint32_t bfr[4];
                ldsm_x4(bfr, sW[cur] + ldBo + (uint32_t)(np * 16 * STRA + ks * 16) * 2);
                mma_bf16(acc[0][np * 2],     afr[0], bfr);
                mma_bf16(acc[1][np * 2],     afr[1], bfr);
                mma_bf16(acc[0][np * 2 + 1], afr[0], bfr + 2);
                mma_bf16(acc[1][np * 2 + 1], afr[1], bfr + 2);
            }
        }
        if (kc + 1 < NCHUNK) CP_WAIT0();
        __syncthreads();
    }
}

// ---------------- kernel 0: W -> bf16 ----------------
__global__ void k_prep(const float* __restrict__ W) {
    int i = blockIdx.x * blockDim.x + threadIdx.x;
    if (i < DIMD * HH) g_Wb[i] = __float2bfloat16(W[i]);
}

// ---------------- kernel 1: Q projection + L2 normalize -> g_Qb ----------------
__global__ void __launch_bounds__(NTHREADS) k_qproj(const float* __restrict__ Q_emb) {
    extern __shared__ char dyn[];
    uint32_t sb = smem_u32(dyn);
    const int tid = threadIdx.x, lane = tid & 31, w = tid >> 5;
    const int wm = w & 3, wn = w >> 2;

    float acc[2][4][4] = {};
    gemm1(Q_emb + (size_t)blockIdx.x * 128 * HH, sb, acc, tid);

    float* nrm = (float*)(dyn + OFF_NQ);   // 128 x 4 floats
#pragma unroll
    for (int mt = 0; mt < 2; ++mt)
#pragma unroll
        for (int rs = 0; rs < 2; ++rs) {
            int gr = wm * 32 + mt * 16 + rs * 8 + (lane >> 2);
            float s = 0.f;
#pragma unroll
            for (int nt = 0; nt < 4; ++nt) {
                float x = acc[mt][nt][rs * 2], y = acc[mt][nt][rs * 2 + 1];
                s = fmaf(x, x, fmaf(y, y, s));
            }
            s += __shfl_xor_sync(0xFFFFFFFFu, s, 1);
            s += __shfl_xor_sync(0xFFFFFFFFu, s, 2);
            if ((lane & 3) == 0) nrm[gr * 4 + wn] = s;
        }
    __syncthreads();
    if (tid < 128) {
        float s = nrm[tid * 4] + nrm[tid * 4 + 1] + nrm[tid * 4 + 2] + nrm[tid * 4 + 3];
        nrm[tid * 4] = rsqrtf(fmaxf(s, 1e-24f));
    }
    __syncthreads();
#pragma unroll
    for (int mt = 0; mt < 2; ++mt)
#pragma unroll
        for (int rs = 0; rs < 2; ++rs) {
            int gr = wm * 32 + mt * 16 + rs * 8 + (lane >> 2);
            float iv = nrm[gr * 4];
            size_t row = (size_t)blockIdx.x * 128 + gr;
#pragma unroll
            for (int nt = 0; nt < 4; ++nt) {
                int col = wn * 32 + nt * 8 + (lane & 3) * 2;
                uint32_t p = packbf2(acc[mt][nt][rs * 2] * iv, acc[mt][nt][rs * 2 + 1] * iv);
                *(uint32_t*)(g_Qb + row * DIMD + col) = p;
            }
        }
}

// ---------------- kernel 2: D projection + scoring ----------------
__global__ void __launch_bounds__(NTHREADS)
k_dscore(const float* __restrict__ D_emb,
         const int* __restrict__ doc_ids,
         const int* __restrict__ doc_attn) {
    extern __shared__ char dyn[];
    uint32_t sb = smem_u32(dyn);
    const int tid = threadIdx.x, lane = tid & 31, w = tid >> 5;
    const int wm = w & 3, wn = w >> 2;
    const int tile = blockIdx.x, b = blockIdx.y;

    // stage Q tile (32 x 128 bf16) into OFF_Q (disjoint from pipeline stages)
    for (int g = tid; g < 512; g += NTHREADS) {
        int qr = g >> 4, qc = (g & 15) * 8;
        uint4 v = *(const uint4*)(g_Qb + ((size_t)b * QLQ + qr) * DIMD + qc);
        *(uint4*)(dyn + OFF_Q + (qr * STRD + qc) * 2) = v;
    }

    float acc[2][4][4] = {};
    gemm1(D_emb + ((size_t)b * DLD + (size_t)tile * 128) * HH, sb, acc, tid);
    __syncthreads();   // all warps done with stage smem before D overlay

    float* nrm = (float*)(dyn + OFF_N);
    const uint32_t sD = sb + OFF_D;
    // epilogue 1: row sq-sums + bf16 convert into smem D tile
#pragma unroll
    for (int mt = 0; mt < 2; ++mt)
#pragma unroll
        for (int rs = 0; rs < 2; ++rs) {
            int gr = wm * 32 + mt * 16 + rs * 8 + (lane >> 2);
            float s = 0.f;
#pragma unroll
            for (int nt = 0; nt < 4; ++nt) {
                float x = acc[mt][nt][rs * 2], y = acc[mt][nt][rs * 2 + 1];
                s = fmaf(x, x, fmaf(y, y, s));
                int col = wn * 32 + nt * 8 + (lane & 3) * 2;
                uint32_t p = packbf2(x, y);
                asm volatile("st.shared.b32 [%0], %1;"
                             :: "r"(sD + (uint32_t)(gr * STRD + col) * 2), "r"(p) : "memory");
            }
            s += __shfl_xor_sync(0xFFFFFFFFu, s, 1);
            s += __shfl_xor_sync(0xFFFFFFFFu, s, 2);
            if ((lane & 3) == 0) nrm[gr * 4 + wn] = s;
        }
    __syncthreads();
    if (tid < 128) {
        float s = nrm[tid * 4] + nrm[tid * 4 + 1] + nrm[tid * 4 + 2] + nrm[tid * 4 + 3];
        nrm[tid * 4] = rsqrtf(fmaxf(s, 1e-24f));
    }
    __syncthreads();

    // GEMM2 (warps 0-7): [128 tokens x 32 queries] = D_tile @ Q_tile^T, K=128
    if (w < 8) {
        const uint32_t sQ = sb + OFF_Q;
        const uint32_t ldA2 = sD + (uint32_t)((w * 16 + (lane & 15)) * STRD
                                              + (lane >> 4) * 8) * 2;
        const uint32_t ldB2 = sQ + (uint32_t)((((lane >> 4) & 1) * 8 + (lane & 7)) * STRD
                                              + ((lane >> 3) & 1) * 8) * 2;
        float acc2[4][4] = {};
#pragma unroll
        for (int ks = 0; ks < 8; ++ks) {
            uint32_t afr[4];
            ldsm_x4(afr, ldA2 + (uint32_t)(ks * 16) * 2);
#pragma unroll
            for (int np = 0; np < 2; ++np) {
                uint32_t bfr[4];
                ldsm_x4(bfr, ldB2 + (uint32_t)(np * 16 * STRD + ks * 16) * 2);
                mma_bf16(acc2[np * 2],     afr, bfr);
                mma_bf16(acc2[np * 2 + 1], afr, bfr + 2);
            }
        }

        const int tb = b * DLD + tile * 128;
        const int r0 = w * 16 + (lane >> 2), r1 = r0 + 8;
        const float iv0 = nrm[r0 * 4], iv1 = nrm[r1 * 4];
        const int id0 = doc_ids[tb + r0], id1 = doc_ids[tb + r1];
        const int at0 = doc_attn[tb + r0], at1 = doc_attn[tb + r1];
        float colmax[8];
#pragma unroll
        for (int nt = 0; nt < 4; ++nt)
#pragma unroll
            for (int c = 0; c < 2; ++c) {
                float v0 = at0 ? (id0 ? fmaf(2.f * iv0, acc2[nt][c], -2.f) : -1.f) : NEGV;
                float v1 = at1 ? (id1 ? fmaf(2.f * iv1, acc2[nt][2 + c], -2.f) : -1.f) : NEGV;
                colmax[nt * 2 + c] = fmaxf(v0, v1);
            }
#pragma unroll
        for (int s = 4; s < 32; s <<= 1)
#pragma unroll
            for (int j = 0; j < 8; ++j)
                colmax[j] = fmaxf(colmax[j], __shfl_xor_sync(0xFFFFFFFFu, colmax[j], s));

        float* red = (float*)(dyn + OFF_R);
        if (lane < 4)
#pragma unroll
            for (int nt = 0; nt < 4; ++nt)
#pragma unroll
                for (int c = 0; c < 2; ++c)
                    red[w * 32 + nt * 8 + lane * 2 + c] = colmax[nt * 2 + c];
    }
    __syncthreads();
    if (tid < 32) {
        float* red = (float*)(dyn + OFF_R);
        float m = -3.0e38f;
#pragma unroll
        for (int ww = 0; ww < 8; ++ww) m = fmaxf(m, red[ww * 32 + tid]);
        g_part[((size_t)b * NTILE + tile) * QLQ + tid] = m;
    }
}

// ---------------- kernel 3: combine tiles -> out[B] ----------------
__global__ void k_final(float* __restrict__ out) {
    int b = blockIdx.x, q = threadIdx.x;
    float m = -3.0e38f;
#pragma unroll
    for (int t = 0; t < NTILE; ++t)
        m = fmaxf(m, g_part[((size_t)b * NTILE + t) * QLQ + q]);
#pragma unroll
    for (int s = 16; s > 0; s >>= 1)
        m += __shfl_xor_sync(0xFFFFFFFFu, m, s);
    if (q == 0) out[b] = m;
}

// ---------------- launch ----------------
extern "C" void kernel_launch(void* const* d_in, const int* in_sizes, int n_in,
                              void* d_out, int out_size) {
    const float* Q_emb = (const float*)d_in[0];
    const float* D_emb = (const float*)d_in[1];
    const int*   ids   = (const int*)d_in[2];
    const int*   attn  = (const int*)d_in[3];
    const float* W     = (const float*)d_in[4];
    float* out = (float*)d_out;

    cudaFuncSetAttribute(k_qproj,  cudaFuncAttributeMaxDynamicSharedMemorySize, SMEM_QP);
    cudaFuncSetAttribute(k_dscore, cudaFuncAttributeMaxDynamicSharedMemorySize, SMEM_DS);

    k_prep<<<(DIMD * HH + 255) / 256, 256>>>(W);
    k_qproj<<<32, NTHREADS, SMEM_QP>>>(Q_emb);
    k_dscore<<<dim3(NTILE, BB), NTHREADS, SMEM_DS>>>(D_emb, ids, attn);
    k_final<<<BB, 32>>>(out);
}

// round 10
// speedup vs baseline: 1.5200x; 1.1325x over previous
#include <cuda_runtime.h>
#include <cuda_bf16.h>
#include <cstdint>

// ---------------- problem constants ----------------
#define BB    128
#define QLQ   32
#define DLD   1024
#define HH    768
#define DIMD  128
#define KC    64          // K elements per chunk
#define NCHUNK 12         // 768 / 64
#define NTILE 8           // 1024 / 128
#define NEGV  (-100000.0f)
#define NTHREADS 512

// padded smem strides (bf16 elements)
#define STRA  72          // A/W tiles: 64 cols + 8 pad (144 B/row)
#define STRD  136         // D/Q tiles: 128 cols + 8 pad (272 B/row)

// smem layout (byte offsets) — THREE stages of (A,W)
#define OFF_S0A  0u
#define OFF_S0W  18432u
#define OFF_S1A  36864u
#define OFF_S1W  55296u
#define OFF_S2A  73728u
#define OFF_S2W  92160u                // stages end 110592
#define OFF_D    0u                    // D tile 128 x STRD bf16 = 34816 (overlays stage0)
#define OFF_Q    110592u               // 32 x STRD bf16 = 8704  (end 119296)
#define OFF_N    119296u               // 128 x 4 float  = 2048  (end 121344)
#define OFF_R    121344u               // 8 x 32 float   = 1024  (end 122368)
#define SMEM_DS  122368
#define OFF_NQ   110592u
#define SMEM_QP  112640

// ---------------- device scratch ----------------
__device__ __align__(16) __nv_bfloat16 g_Wb[DIMD * HH];          // 192 KB
__device__ __align__(16) __nv_bfloat16 g_Qb[BB * QLQ * DIMD];    // 1 MB
__device__ float g_part[BB * NTILE * QLQ];                       // 128 KB

// ---------------- helpers ----------------
static __device__ __forceinline__ uint32_t smem_u32(const void* p) {
    uint32_t a;
    asm("{ .reg .u64 t; cvta.to.shared.u64 t, %1; cvt.u32.u64 %0, t; }"
        : "=r"(a) : "l"(p));
    return a;
}
static __device__ __forceinline__ void ldsm_x4(uint32_t (&r)[4], uint32_t addr) {
    asm volatile("ldmatrix.sync.aligned.m8n8.x4.shared.b16 {%0,%1,%2,%3}, [%4];"
                 : "=r"(r[0]), "=r"(r[1]), "=r"(r[2]), "=r"(r[3]) : "r"(addr));
}
static __device__ __forceinline__ void mma_bf16(float (&d)[4], const uint32_t (&a)[4],
                                                const uint32_t* b) {
    asm volatile("mma.sync.aligned.m16n8k16.row.col.f32.bf16.bf16.f32 "
                 "{%0,%1,%2,%3}, {%4,%5,%6,%7}, {%8,%9}, {%0,%1,%2,%3};"
                 : "+f"(d[0]), "+f"(d[1]), "+f"(d[2]), "+f"(d[3])
                 : "r"(a[0]), "r"(a[1]), "r"(a[2]), "r"(a[3]), "r"(b[0]), "r"(b[1]));
}
static __device__ __forceinline__ uint32_t packbf2(float lo, float hi) {
    __nv_bfloat162 v = __floats2bfloat162_rn(lo, hi);
    return *reinterpret_cast<uint32_t*>(&v);
}
static __device__ __forceinline__ void cp16(uint32_t dst, const void* src) {
    asm volatile("cp.async.cg.shared.global [%0], [%1], 16;"
                 :: "r"(dst), "l"(src) : "memory");
}
#define CP_COMMIT() asm volatile("cp.async.commit_group;" ::: "memory")
#define CP_WAIT(n)  asm volatile("cp.async.wait_group %0;" :: "n"(n) : "memory")

// conflict-free A staging: 16 bf16 per thread as two STS.128
static __device__ __forceinline__ void stage_A(uint32_t dst, const float4 (&af)[4]) {
    uint32_t p[8];
#pragma unroll
    for (int i = 0; i < 4; ++i) {
        p[2 * i]     = packbf2(af[i].x, af[i].y);
        p[2 * i + 1] = packbf2(af[i].z, af[i].w);
    }
    asm volatile("st.shared.v4.b32 [%0], {%1, %2, %3, %4};"
                 :: "r"(dst), "r"(p[0]), "r"(p[1]), "r"(p[2]), "r"(p[3]) : "memory");
    asm volatile("st.shared.v4.b32 [%0], {%1, %2, %3, %4};"
                 :: "r"(dst + 16u), "r"(p[4]), "r"(p[5]), "r"(p[6]), "r"(p[7]) : "memory");
}

// ---------------- GEMM1 mainloop (3-stage pipeline, ldsm double-buffer) ----------------
static __device__ __forceinline__ void gemm1(const float* __restrict__ a_rows,
                                             uint32_t sb,
                                             float (&acc)[2][4][4], int tid) {
    const int lane = tid & 31, w = tid >> 5;
    const int wm = w & 3, wn = w >> 2;
    const int lr = tid >> 2;                    // 0..127 load row
    const int lc = (tid & 3) * 16;              // 0,16,32,48
    const float* aptr = a_rows + (size_t)lr * HH + lc;
    const __nv_bfloat16* wsrc = g_Wb + (size_t)lr * HH + lc;

    const uint32_t sA[3] = {sb + OFF_S0A, sb + OFF_S1A, sb + OFF_S2A};
    const uint32_t sW[3] = {sb + OFF_S0W, sb + OFF_S1W, sb + OFF_S2W};
    const uint32_t stO = (uint32_t)(lr * STRA + lc) * 2;
    const uint32_t ldAo = (uint32_t)((wm * 32 + (lane & 15)) * STRA + (lane >> 4) * 8) * 2;
    const uint32_t ldBo = (uint32_t)((wn * 32 + ((lane >> 4) & 1) * 8 + (lane & 7)) * STRA
                                     + ((lane >> 3) & 1) * 8) * 2;

    float4 af[4];
    // ---- prologue: chunks 0,1 staged; chunk 2 in regs; W0 awaited
#pragma unroll
    for (int i = 0; i < 4; ++i) af[i] = *(const float4*)(aptr + i * 4);
    stage_A(sA[0] + stO, af);
    cp16(sW[0] + stO, wsrc);
    cp16(sW[0] + stO + 16u, wsrc + 8);
    CP_COMMIT();
#pragma unroll
    for (int i = 0; i < 4; ++i) af[i] = *(const float4*)(aptr + KC + i * 4);
    stage_A(sA[1] + stO, af);
    cp16(sW[1] + stO, wsrc + KC);
    cp16(sW[1] + stO + 16u, wsrc + KC + 8);
    CP_COMMIT();
#pragma unroll
    for (int i = 0; i < 4; ++i) af[i] = *(const float4*)(aptr + 2 * KC + i * 4);
    CP_WAIT(1);
    __syncthreads();

    for (int kc = 0; kc < NCHUNK; ++kc) {
        const int cur = kc % 3;
        if (kc + 2 < NCHUNK) {
            const int ns = (kc + 2) % 3;
            stage_A(sA[ns] + stO, af);           // af holds chunk kc+2
            const __nv_bfloat16* wp = wsrc + (kc + 2) * KC;
            cp16(sW[ns] + stO, wp);
            cp16(sW[ns] + stO + 16u, wp + 8);
            CP_COMMIT();
            if (kc + 3 < NCHUNK) {
                const float* ap = aptr + (kc + 3) * KC;
#pragma unroll
                for (int i = 0; i < 4; ++i) af[i] = *(const float4*)(ap + i * 4);
            }
        }
        // ---- MMA on stage cur, ldsm double-buffered across ks
        {
            uint32_t afr[2][2][4], bfr[2][2][4];
#pragma unroll
            for (int mt = 0; mt < 2; ++mt)
                ldsm_x4(afr[0][mt], sA[cur] + ldAo + (uint32_t)(mt * 16 * STRA) * 2);
#pragma unroll
            for (int np = 0; np < 2; ++np)
                ldsm_x4(bfr[0][np], sW[cur] + ldBo + (uint32_t)(np * 16 * STRA) * 2);
#pragma unroll
            for (int ks = 0; ks < 4; ++ks) {
                const int cb = ks & 1, nb = cb ^ 1;
                if (ks < 3) {
#pragma unroll
                    for (int mt = 0; mt < 2; ++mt)
                        ldsm_x4(afr[nb][mt], sA[cur] + ldAo
                                + (uint32_t)(mt * 16 * STRA + (ks + 1) * 16) * 2);
#pragma unroll
                    for (int np = 0; np < 2; ++np)
                        ldsm_x4(bfr[nb][np], sW[cur] + ldBo
                                + (uint32_t)(np * 16 * STRA + (ks + 1) * 16) * 2);
                }
#pragma unroll
                for (int np = 0; np < 2; ++np) {
                    mma_bf16(acc[0][np * 2],     afr[cb][0], bfr[cb][np]);
                    mma_bf16(acc[1][np * 2],     afr[cb][1], bfr[cb][np]);
                    mma_bf16(acc[0][np * 2 + 1], afr[cb][0], bfr[cb][np] + 2);
                    mma_bf16(acc[1][np * 2 + 1], afr[cb][1], bfr[cb][np] + 2);
                }
            }
        }
        if (kc + 2 < NCHUNK) CP_WAIT(1); else CP_WAIT(0);
        __syncthreads();
    }
}

// ---------------- kernel 0: W -> bf16 ----------------
__global__ void k_prep(const float* __restrict__ W) {
    int i = blockIdx.x * blockDim.x + threadIdx.x;
    if (i < DIMD * HH) g_Wb[i] = __float2bfloat16(W[i]);
}

// ---------------- kernel 1: Q projection + L2 normalize -> g_Qb ----------------
__global__ void __launch_bounds__(NTHREADS) k_qproj(const float* __restrict__ Q_emb) {
    extern __shared__ char dyn[];
    uint32_t sb = smem_u32(dyn);
    const int tid = threadIdx.x, lane = tid & 31, w = tid >> 5;
    const int wm = w & 3, wn = w >> 2;

    float acc[2][4][4] = {};
    gemm1(Q_emb + (size_t)blockIdx.x * 128 * HH, sb, acc, tid);

    float* nrm = (float*)(dyn + OFF_NQ);
#pragma unroll
    for (int mt = 0; mt < 2; ++mt)
#pragma unroll
        for (int rs = 0; rs < 2; ++rs) {
            int gr = wm * 32 + mt * 16 + rs * 8 + (lane >> 2);
            float s = 0.f;
#pragma unroll
            for (int nt = 0; nt < 4; ++nt) {
                float x = acc[mt][nt][rs * 2], y = acc[mt][nt][rs * 2 + 1];
                s = fmaf(x, x, fmaf(y, y, s));
            }
            s += __shfl_xor_sync(0xFFFFFFFFu, s, 1);
            s += __shfl_xor_sync(0xFFFFFFFFu, s, 2);
            if ((lane & 3) == 0) nrm[gr * 4 + wn] = s;
        }
    __syncthreads();
    if (tid < 128) {
        float s = nrm[tid * 4] + nrm[tid * 4 + 1] + nrm[tid * 4 + 2] + nrm[tid * 4 + 3];
        nrm[tid * 4] = rsqrtf(fmaxf(s, 1e-24f));
    }
    __syncthreads();
#pragma unroll
    for (int mt = 0; mt < 2; ++mt)
#pragma unroll
        for (int rs = 0; rs < 2; ++rs) {
            int gr = wm * 32 + mt * 16 + rs * 8 + (lane >> 2);
            float iv = nrm[gr * 4];
            size_t row = (size_t)blockIdx.x * 128 + gr;
#pragma unroll
            for (int nt = 0; nt < 4; ++nt) {
                int col = wn * 32 + nt * 8 + (lane & 3) * 2;
                uint32_t p = packbf2(acc[mt][nt][rs * 2] * iv, acc[mt][nt][rs * 2 + 1] * iv);
                *(uint32_t*)(g_Qb + row * DIMD + col) = p;
            }
        }
}

// ---------------- kernel 2: D projection + scoring ----------------
__global__ void __launch_bounds__(NTHREADS)
k_dscore(const float* __restrict__ D_emb,
         const int* __restrict__ doc_ids,
         const int* __restrict__ doc_attn) {
    extern __shared__ char dyn[];
    uint32_t sb = smem_u32(dyn);
    const int tid = threadIdx.x, lane = tid & 31, w = tid >> 5;
    const int wm = w & 3, wn = w >> 2;
    const int tile = blockIdx.x, b = blockIdx.y;

    // stage Q tile (32 x 128 bf16) into OFF_Q (disjoint from pipeline stages)
    for (int g = tid; g < 512; g += NTHREADS) {
        int qr = g >> 4, qc = (g & 15) * 8;
        uint4 v = *(const uint4*)(g_Qb + ((size_t)b * QLQ + qr) * DIMD + qc);
        *(uint4*)(dyn + OFF_Q + (qr * STRD + qc) * 2) = v;
    }

    float acc[2][4][4] = {};
    gemm1(D_emb + ((size_t)b * DLD + (size_t)tile * 128) * HH, sb, acc, tid);
    // gemm1 ends with __syncthreads: all stage reads complete -> D overlay safe

    float* nrm = (float*)(dyn + OFF_N);
    const uint32_t sD = sb + OFF_D;
    // epilogue 1: row sq-sums + bf16 convert into smem D tile
#pragma unroll
    for (int mt = 0; mt < 2; ++mt)
#pragma unroll
        for (int rs = 0; rs < 2; ++rs) {
            int gr = wm * 32 + mt * 16 + rs * 8 + (lane >> 2);
            float s = 0.f;
#pragma unroll
            for (int nt = 0; nt < 4; ++nt) {
                float x = acc[mt][nt][rs * 2], y = acc[mt][nt][rs * 2 + 1];
                s = fmaf(x, x, fmaf(y, y, s));
                int col = wn * 32 + nt * 8 + (lane & 3) * 2;
                uint32_t p = packbf2(x, y);
                asm volatile("st.shared.b32 [%0], %1;"
                             :: "r"(sD + (uint32_t)(gr * STRD + col) * 2), "r"(p) : "memory");
            }
            s += __shfl_xor_sync(0xFFFFFFFFu, s, 1);
            s += __shfl_xor_sync(0xFFFFFFFFu, s, 2);
            if ((lane & 3) == 0) nrm[gr * 4 + wn] = s;
        }
    __syncthreads();
    if (tid < 128) {
        float s = nrm[tid * 4] + nrm[tid * 4 + 1] + nrm[tid * 4 + 2] + nrm[tid * 4 + 3];
        nrm[tid * 4] = rsqrtf(fmaxf(s, 1e-24f));
    }
    __syncthreads();

    // GEMM2 (warps 0-7): [128 tokens x 32 queries] = D_tile @ Q_tile^T, K=128
    if (w < 8) {
        const uint32_t sQ = sb + OFF_Q;
        const uint32_t ldA2 = sD + (uint32_t)((w * 16 + (lane & 15)) * STRD
                                              + (lane >> 4) * 8) * 2;
        const uint32_t ldB2 = sQ + (uint32_t)((((lane >> 4) & 1) * 8 + (lane & 7)) * STRD
                                              + ((lane >> 3) & 1) * 8) * 2;
        float acc2[4][4] = {};
#pragma unroll
        for (int ks = 0; ks < 8; ++ks) {
            uint32_t afr[4];
            ldsm_x4(afr, ldA2 + (uint32_t)(ks * 16) * 2);
#pragma unroll
            for (int np = 0; np < 2; ++np) {
                uint32_t bfr[4];
                ldsm_x4(bfr, ldB2 + (uint32_t)(np * 16 * STRD + ks * 16) * 2);
                mma_bf16(acc2[np * 2],     afr, bfr);
                mma_bf16(acc2[np * 2 + 1], afr, bfr + 2);
            }
        }

        const int tb = b * DLD + tile * 128;
        const int r0 = w * 16 + (lane >> 2), r1 = r0 + 8;
        const float iv0 = nrm[r0 * 4], iv1 = nrm[r1 * 4];
        const int id0 = doc_ids[tb + r0], id1 = doc_ids[tb + r1];
        const int at0 = doc_attn[tb + r0], at1 = doc_attn[tb + r1];
        float colmax[8];
#pragma unroll
        for (int nt = 0; nt < 4; ++nt)
#pragma unroll
            for (int c = 0; c < 2; ++c) {
                float v0 = at0 ? (id0 ? fmaf(2.f * iv0, acc2[nt][c], -2.f) : -1.f) : NEGV;
                float v1 = at1 ? (id1 ? fmaf(2.f * iv1, acc2[nt][2 + c], -2.f) : -1.f) : NEGV;
                colmax[nt * 2 + c] = fmaxf(v0, v1);
            }
#pragma unroll
        for (int s = 4; s < 32; s <<= 1)
#pragma unroll
            for (int j = 0; j < 8; ++j)
                colmax[j] = fmaxf(colmax[j], __shfl_xor_sync(0xFFFFFFFFu, colmax[j], s));

        float* red = (float*)(dyn + OFF_R);
        if (lane < 4)
#pragma unroll
            for (int nt = 0; nt < 4; ++nt)
#pragma unroll
                for (int c = 0; c < 2; ++c)
                    red[w * 32 + nt * 8 + lane * 2 + c] = colmax[nt * 2 + c];
    }
    __syncthreads();
    if (tid < 32) {
        float* red = (float*)(dyn + OFF_R);
        float m = -3.0e38f;
#pragma unroll
        for (int ww = 0; ww < 8; ++ww) m = fmaxf(m, red[ww * 32 + tid]);
        g_part[((size_t)b * NTILE + tile) * QLQ + tid] = m;
    }
}

// ---------------- kernel 3: combine tiles -> out[B] ----------------
__global__ void k_final(float* __restrict__ out) {
    int b = blockIdx.x, q = threadIdx.x;
    float m = -3.0e38f;
#pragma unroll
    for (int t = 0; t < NTILE; ++t)
        m = fmaxf(m, g_part[((size_t)b * NTILE + t) * QLQ + q]);
#pragma unroll
    for (int s = 16; s > 0; s >>= 1)
        m += __shfl_xor_sync(0xFFFFFFFFu, m, s);
    if (q == 0) out[b] = m;
}

// ---------------- launch ----------------
extern "C" void kernel_launch(void* const* d_in, const int* in_sizes, int n_in,
                              void* d_out, int out_size) {
    const float* Q_emb = (const float*)d_in[0];
    const float* D_emb = (const float*)d_in[1];
    const int*   ids   = (const int*)d_in[2];
    const int*   attn  = (const int*)d_in[3];
    const float* W     = (const float*)d_in[4];
    float* out = (float*)d_out;

    cudaFuncSetAttribute(k_qproj,  cudaFuncAttributeMaxDynamicSharedMemorySize, SMEM_QP);
    cudaFuncSetAttribute(k_dscore, cudaFuncAttributeMaxDynamicSharedMemorySize, SMEM_DS);

    k_prep<<<(DIMD * HH + 255) / 256, 256>>>(W);
    k_qproj<<<32, NTHREADS, SMEM_QP>>>(Q_emb);
    k_dscore<<<dim3(NTILE, BB), NTHREADS, SMEM_DS>>>(D_emb, ids, attn);
    k_final<<<BB, 32>>>(out);
}